// round 16
// baseline (speedup 1.0000x reference)
#include <cuda_runtime.h>
#include <cuda_bf16.h>
#include <math_constants.h>

#define N_SAMPLING 32
#define N_FINAL    8
#define C_DEPTH    128
#define H_DIM      128
#define W_DIM      128
#define N_LINES    50000
#define PIX        (H_DIM * W_DIM)          // 16384
#define LINES_PER_BLOCK 4

// 8 MB scratch: features transposed to [H*W][C] (channel-contiguous per pixel).
// float4 view: [pix][32] float4.
__device__ float4 g_featT[PIX * (C_DEPTH / 4)];

// ---------------------------------------------------------------------------
// Transpose [C, H*W] -> [H*W, C] with a 32x32 shared tile (coalesced both ways)
// grid: (PIX/32, C/32), block: (32, 8)
// ---------------------------------------------------------------------------
__global__ void transpose_chw_to_hwc(const float* __restrict__ f) {
    __shared__ float tile[32][33];
    const int pix0 = blockIdx.x * 32;
    const int c0   = blockIdx.y * 32;
    const int tx = threadIdx.x, ty = threadIdx.y;

    float* ft = reinterpret_cast<float*>(g_featT);

#pragma unroll
    for (int i = 0; i < 4; ++i) {
        int c = c0 + ty + i * 8;                       // channel (row of tile)
        tile[ty + i * 8][tx] = f[c * PIX + pix0 + tx]; // coalesced read over pix
    }
    __syncthreads();
#pragma unroll
    for (int i = 0; i < 4; ++i) {
        int pix = pix0 + ty + i * 8;
        ft[pix * C_DEPTH + c0 + tx] = tile[tx][ty + i * 8]; // coalesced write over c
    }
}

// ---------------------------------------------------------------------------
// Main kernel: 4 lines per 128-thread block; 32 lanes per line, each lane owns
// 4 channels (float4). Sample coords/weights precomputed into shared by the
// 32 lanes of each line (one sample per lane).
// ---------------------------------------------------------------------------
__global__ __launch_bounds__(128)
void line_pooling_kernel(const float* __restrict__ lines,
                         float* __restrict__ out) {
    __shared__ int4   s_idx[LINES_PER_BLOCK][N_SAMPLING];  // float4-unit base offsets of 4 corners
    __shared__ float4 s_wt [LINES_PER_BLOCK][N_SAMPLING];  // matching bilinear weights

    const int tid  = threadIdx.x;
    const int l    = tid >> 5;         // line slot in block (0..3)
    const int lane = tid & 31;         // channel-group / sample id
    const int line = blockIdx.x * LINES_PER_BLOCK + l;

    // ---- precompute sample 'lane' for line 'l' ----
    {
        const float4 ln = *reinterpret_cast<const float4*>(lines + (size_t)line * 4);
        const float t   = (float)lane / 31.0f;
        const float omt = 1.0f - t;
        const float px  = ln.x * t + ln.z * omt - 0.5f;
        const float py  = ln.y * t + ln.w * omt - 0.5f;

        const float px0f = fminf(fmaxf(floorf(px), 0.0f), (float)(W_DIM - 1));
        const float py0f = fminf(fmaxf(floorf(py), 0.0f), (float)(H_DIM - 1));
        const float px1f = fminf(px0f + 1.0f, (float)(W_DIM - 1));
        const float py1f = fminf(py0f + 1.0f, (float)(H_DIM - 1));

        const int x0 = (int)px0f, y0 = (int)py0f;
        const int x1 = (int)px1f, y1 = (int)py1f;

        const float wx0 = px1f - px;   // weight for x0 column
        const float wx1 = px  - px0f;  // weight for x1 column
        const float wy0 = py1f - py;   // weight for y0 row
        const float wy1 = py  - py0f;  // weight for y1 row

        // corner order: (y0,x0), (y1,x0), (y0,x1), (y1,x1)  — matches reference
        s_idx[l][lane] = make_int4((y0 * W_DIM + x0) * (C_DEPTH / 4),
                                   (y1 * W_DIM + x0) * (C_DEPTH / 4),
                                   (y0 * W_DIM + x1) * (C_DEPTH / 4),
                                   (y1 * W_DIM + x1) * (C_DEPTH / 4));
        s_wt [l][lane] = make_float4(wy0 * wx0, wy1 * wx0, wy0 * wx1, wy1 * wx1);
    }
    __syncthreads();

    // ---- gather + pool ----
    const float4* __restrict__ T = g_featT;

    float m[4][N_FINAL];   // [channel-within-lane][final]
#pragma unroll
    for (int cl = 0; cl < 4; ++cl)
#pragma unroll
        for (int g = 0; g < N_FINAL; ++g)
            m[cl][g] = -CUDART_INF_F;

#pragma unroll
    for (int g = 0; g < N_FINAL; ++g) {
#pragma unroll
        for (int j = 0; j < 4; ++j) {
            const int s = g * 4 + j;
            const int4   p = s_idx[l][s];
            const float4 w = s_wt [l][s];

            const float4 f00 = T[p.x + lane];
            const float4 f10 = T[p.y + lane];
            const float4 f01 = T[p.z + lane];
            const float4 f11 = T[p.w + lane];

            const float v0 = w.x * f00.x + w.y * f10.x + w.z * f01.x + w.w * f11.x;
            const float v1 = w.x * f00.y + w.y * f10.y + w.z * f01.y + w.w * f11.y;
            const float v2 = w.x * f00.z + w.y * f10.z + w.z * f01.z + w.w * f11.z;
            const float v3 = w.x * f00.w + w.y * f10.w + w.z * f01.w + w.w * f11.w;

            m[0][g] = fmaxf(m[0][g], v0);
            m[1][g] = fmaxf(m[1][g], v1);
            m[2][g] = fmaxf(m[2][g], v2);
            m[3][g] = fmaxf(m[3][g], v3);
        }
    }

    // ---- write: channels 4*lane..4*lane+3, each 8 finals contiguous ----
    float* ob = out + (size_t)line * (N_FINAL * C_DEPTH) + lane * 32;
#pragma unroll
    for (int cl = 0; cl < 4; ++cl) {
        float4 lo = make_float4(m[cl][0], m[cl][1], m[cl][2], m[cl][3]);
        float4 hi = make_float4(m[cl][4], m[cl][5], m[cl][6], m[cl][7]);
        *reinterpret_cast<float4*>(ob + cl * 8)     = lo;
        *reinterpret_cast<float4*>(ob + cl * 8 + 4) = hi;
    }
}

extern "C" void kernel_launch(void* const* d_in, const int* in_sizes, int n_in,
                              void* d_out, int out_size) {
    const float* features = (const float*)d_in[0];   // [128, 128, 128] fp32
    const float* lines    = (const float*)d_in[1];   // [50000, 4] fp32
    float* out            = (float*)d_out;           // [50000, 1024] fp32

    (void)in_sizes; (void)n_in; (void)out_size;

    dim3 tgrid(PIX / 32, C_DEPTH / 32);
    dim3 tblk(32, 8);
    transpose_chw_to_hwc<<<tgrid, tblk>>>(features);

    line_pooling_kernel<<<N_LINES / LINES_PER_BLOCK, 128>>>(lines, out);
}

// round 17
// speedup vs baseline: 1.0004x; 1.0004x over previous
#include <cuda_runtime.h>
#include <cuda_bf16.h>
#include <math_constants.h>

#define N_SAMPLING 32
#define N_FINAL    8
#define C_DEPTH    128
#define H_DIM      128
#define W_DIM      128
#define N_LINES    50000
#define PIX        (H_DIM * W_DIM)          // 16384
#define LINES_PER_BLOCK 4

// 8 MB scratch: features transposed to [H*W][C] (channel-contiguous per pixel).
// float4 view: [pix][32] float4.
__device__ float4 g_featT[PIX * (C_DEPTH / 4)];

// ---------------------------------------------------------------------------
// Transpose [C, H*W] -> [H*W, C] with a 32x32 shared tile (coalesced both ways)
// grid: (PIX/32, C/32), block: (32, 8)
// ---------------------------------------------------------------------------
__global__ void transpose_chw_to_hwc(const float* __restrict__ f) {
    __shared__ float tile[32][33];
    const int pix0 = blockIdx.x * 32;
    const int c0   = blockIdx.y * 32;
    const int tx = threadIdx.x, ty = threadIdx.y;

    float* ft = reinterpret_cast<float*>(g_featT);

#pragma unroll
    for (int i = 0; i < 4; ++i) {
        int c = c0 + ty + i * 8;                       // channel (row of tile)
        tile[ty + i * 8][tx] = f[c * PIX + pix0 + tx]; // coalesced read over pix
    }
    __syncthreads();
#pragma unroll
    for (int i = 0; i < 4; ++i) {
        int pix = pix0 + ty + i * 8;
        ft[pix * C_DEPTH + c0 + tx] = tile[tx][ty + i * 8]; // coalesced write over c
    }
}

// ---------------------------------------------------------------------------
// Main kernel: 4 lines per 128-thread block; 32 lanes per line, each lane owns
// 4 channels (float4). Sample coords/weights precomputed into shared by the
// 32 lanes of each line (one sample per lane).
// ---------------------------------------------------------------------------
__global__ __launch_bounds__(128)
void line_pooling_kernel(const float* __restrict__ lines,
                         float* __restrict__ out) {
    __shared__ int4   s_idx[LINES_PER_BLOCK][N_SAMPLING];  // float4-unit base offsets of 4 corners
    __shared__ float4 s_wt [LINES_PER_BLOCK][N_SAMPLING];  // matching bilinear weights

    const int tid  = threadIdx.x;
    const int l    = tid >> 5;         // line slot in block (0..3)
    const int lane = tid & 31;         // channel-group / sample id
    const int line = blockIdx.x * LINES_PER_BLOCK + l;

    // ---- precompute sample 'lane' for line 'l' ----
    {
        const float4 ln = *reinterpret_cast<const float4*>(lines + (size_t)line * 4);
        const float t   = (float)lane / 31.0f;
        const float omt = 1.0f - t;
        const float px  = ln.x * t + ln.z * omt - 0.5f;
        const float py  = ln.y * t + ln.w * omt - 0.5f;

        const float px0f = fminf(fmaxf(floorf(px), 0.0f), (float)(W_DIM - 1));
        const float py0f = fminf(fmaxf(floorf(py), 0.0f), (float)(H_DIM - 1));
        const float px1f = fminf(px0f + 1.0f, (float)(W_DIM - 1));
        const float py1f = fminf(py0f + 1.0f, (float)(H_DIM - 1));

        const int x0 = (int)px0f, y0 = (int)py0f;
        const int x1 = (int)px1f, y1 = (int)py1f;

        const float wx0 = px1f - px;   // weight for x0 column
        const float wx1 = px  - px0f;  // weight for x1 column
        const float wy0 = py1f - py;   // weight for y0 row
        const float wy1 = py  - py0f;  // weight for y1 row

        // corner order: (y0,x0), (y1,x0), (y0,x1), (y1,x1)  — matches reference
        s_idx[l][lane] = make_int4((y0 * W_DIM + x0) * (C_DEPTH / 4),
                                   (y1 * W_DIM + x0) * (C_DEPTH / 4),
                                   (y0 * W_DIM + x1) * (C_DEPTH / 4),
                                   (y1 * W_DIM + x1) * (C_DEPTH / 4));
        s_wt [l][lane] = make_float4(wy0 * wx0, wy1 * wx0, wy0 * wx1, wy1 * wx1);
    }
    __syncthreads();

    // ---- gather + pool ----
    const float4* __restrict__ T = g_featT;

    float m[4][N_FINAL];   // [channel-within-lane][final]
#pragma unroll
    for (int cl = 0; cl < 4; ++cl)
#pragma unroll
        for (int g = 0; g < N_FINAL; ++g)
            m[cl][g] = -CUDART_INF_F;

#pragma unroll
    for (int g = 0; g < N_FINAL; ++g) {
#pragma unroll
        for (int j = 0; j < 4; ++j) {
            const int s = g * 4 + j;
            const int4   p = s_idx[l][s];
            const float4 w = s_wt [l][s];

            const float4 f00 = T[p.x + lane];
            const float4 f10 = T[p.y + lane];
            const float4 f01 = T[p.z + lane];
            const float4 f11 = T[p.w + lane];

            const float v0 = w.x * f00.x + w.y * f10.x + w.z * f01.x + w.w * f11.x;
            const float v1 = w.x * f00.y + w.y * f10.y + w.z * f01.y + w.w * f11.y;
            const float v2 = w.x * f00.z + w.y * f10.z + w.z * f01.z + w.w * f11.z;
            const float v3 = w.x * f00.w + w.y * f10.w + w.z * f01.w + w.w * f11.w;

            m[0][g] = fmaxf(m[0][g], v0);
            m[1][g] = fmaxf(m[1][g], v1);
            m[2][g] = fmaxf(m[2][g], v2);
            m[3][g] = fmaxf(m[3][g], v3);
        }
    }

    // ---- write: channels 4*lane..4*lane+3, each 8 finals contiguous ----
    float* ob = out + (size_t)line * (N_FINAL * C_DEPTH) + lane * 32;
#pragma unroll
    for (int cl = 0; cl < 4; ++cl) {
        float4 lo = make_float4(m[cl][0], m[cl][1], m[cl][2], m[cl][3]);
        float4 hi = make_float4(m[cl][4], m[cl][5], m[cl][6], m[cl][7]);
        *reinterpret_cast<float4*>(ob + cl * 8)     = lo;
        *reinterpret_cast<float4*>(ob + cl * 8 + 4) = hi;
    }
}

extern "C" void kernel_launch(void* const* d_in, const int* in_sizes, int n_in,
                              void* d_out, int out_size) {
    const float* features = (const float*)d_in[0];   // [128, 128, 128] fp32
    const float* lines    = (const float*)d_in[1];   // [50000, 4] fp32
    float* out            = (float*)d_out;           // [50000, 1024] fp32

    (void)in_sizes; (void)n_in; (void)out_size;

    dim3 tgrid(PIX / 32, C_DEPTH / 32);
    dim3 tblk(32, 8);
    transpose_chw_to_hwc<<<tgrid, tblk>>>(features);

    line_pooling_kernel<<<N_LINES / LINES_PER_BLOCK, 128>>>(lines, out);
}